// round 6
// baseline (speedup 1.0000x reference)
#include <cuda_runtime.h>
#include <math.h>
#include <stdint.h>

#define BB    2
#define TT    2048
#define DD    2048
#define HH    16
#define DK    128
#define N3    (3*DD)
#define MROWS (BB*TT)   // 4096

// ---------------- scratch (device globals; no allocation allowed) ----------------
__device__ float g_kqv[(size_t)MROWS * N3];    // fp32 k|q|v (tf32-rounded, rope applied)
__device__ float g_attn[(size_t)MROWS * DD];   // attention output fp32
__device__ float g_xp[(size_t)MROWS * DD];     // x packed (tf32)   [ck][M] float4 cells
__device__ float g_wkp[(size_t)DD * N3];       // Wkqv packed       [ck][N] float4 cells
__device__ float g_wop[(size_t)DD * DD];       // Wo packed
__device__ float g_ap[(size_t)MROWS * DD];     // attn packed
__device__ float g_inv[64];
__device__ float g_cos[TT * 64];
__device__ float g_sin[TT * 64];

// ---------------- PTX helpers ----------------
__device__ __forceinline__ uint32_t smem_u32(const void* p) {
    return (uint32_t)__cvta_generic_to_shared(p);
}
__device__ __forceinline__ void cp16s(uint32_t dst, const void* src) {
    asm volatile("cp.async.cg.shared.global [%0], [%1], 16;\n" :: "r"(dst), "l"(src));
}
__device__ __forceinline__ void cp16(void* dst, const void* src) {
    asm volatile("cp.async.cg.shared.global [%0], [%1], 16;\n"
                 :: "r"(smem_u32(dst)), "l"(src));
}
__device__ __forceinline__ void cp_commit() {
    asm volatile("cp.async.commit_group;\n");
}
template<int N>
__device__ __forceinline__ void cp_wait() {
    asm volatile("cp.async.wait_group %0;\n" :: "n"(N));
}
__device__ __forceinline__ uint32_t f2tf(float f) {
    uint32_t r;
    asm("cvt.rna.tf32.f32 %0, %1;" : "=r"(r) : "f"(f));
    return r;
}
__device__ __forceinline__ float tfr(float f) {
    return __uint_as_float(f2tf(f));
}
__device__ __forceinline__ void mma_tf32(float c[4],
                                         uint32_t a0, uint32_t a1, uint32_t a2, uint32_t a3,
                                         uint32_t b0, uint32_t b1) {
    asm volatile(
        "mma.sync.aligned.m16n8k8.row.col.f32.tf32.tf32.f32 "
        "{%0,%1,%2,%3}, {%4,%5,%6,%7}, {%8,%9}, {%0,%1,%2,%3};\n"
        : "+f"(c[0]), "+f"(c[1]), "+f"(c[2]), "+f"(c[3])
        : "r"(a0), "r"(a1), "r"(a2), "r"(a3), "r"(b0), "r"(b1));
}
#define FU(x) __float_as_uint(x)

// ---------------- pack kernels: fragment-order gmem layout ----------------
// Cell (ck, i), ck = kg*4+tg, holds (X[i][kb], X[i][kb+4], X[i][kb+8], X[i][kb+12]),
// kb = kg*16+tg, as float4 at out[ck*Len + i]. Values tf32(rna)-rounded.

__global__ void packA_kernel(const float* __restrict__ in, float4* __restrict__ out,
                             int Mt, int K)
{
    __shared__ float tile[32][65];
    const int k0 = blockIdx.x * 64;
    const int m0 = blockIdx.y * 32;
    const int t  = threadIdx.x;
    #pragma unroll
    for (int i = 0; i < 2; i++) {
        int u = t + (i << 8);
        int m = u >> 4;
        int kc = u & 15;
        float4 v = *(const float4*)&in[(size_t)(m0 + m) * K + k0 + kc * 4];
        tile[m][kc * 4 + 0] = v.x;
        tile[m][kc * 4 + 1] = v.y;
        tile[m][kc * 4 + 2] = v.z;
        tile[m][kc * 4 + 3] = v.w;
    }
    __syncthreads();
    #pragma unroll
    for (int i = 0; i < 2; i++) {
        int u  = t + (i << 8);
        int ck = u >> 5;
        int m  = u & 31;
        int kg = ck >> 2, tg = ck & 3;
        int kb = kg * 16 + tg;
        float4 v;
        v.x = tfr(tile[m][kb]);
        v.y = tfr(tile[m][kb + 4]);
        v.z = tfr(tile[m][kb + 8]);
        v.w = tfr(tile[m][kb + 12]);
        out[(size_t)((k0 / 16 + kg) * 4 + tg) * Mt + m0 + m] = v;
    }
}

__global__ void packB_kernel(const float* __restrict__ W, float4* __restrict__ out,
                             int K, int N)
{
    int idx = blockIdx.x * 256 + threadIdx.x;
    int total = (K / 4) * N;
    if (idx >= total) return;
    int ck = idx / N;
    int n  = idx - ck * N;
    int kg = ck >> 2, tg = ck & 3;
    int kb = kg * 16 + tg;
    float4 v;
    v.x = tfr(W[(size_t)kb * N + n]);
    v.y = tfr(W[(size_t)(kb + 4) * N + n]);
    v.z = tfr(W[(size_t)(kb + 8) * N + n]);
    v.w = tfr(W[(size_t)(kb + 12) * N + n]);
    out[(size_t)ck * N + n] = v;
}

// ---------------- packed TF32 GEMM: CTA 128x256, warp tile 64x64, BK=16, 3 stages ----------------
// Stage cells (16B): A 4*130, B 4*258. Strides ≡ 2 mod 8 -> conflict-free LDS.128.
#define ACELLS      520
#define STAGE_CELLS 1552
#define STAGE_BYTES (STAGE_CELLS * 16)       // 24832
#define GEMM_SMEM   (3 * STAGE_BYTES)        // 74496

__global__ __launch_bounds__(256, 1)
void gemm_packed_kernel(const float4* __restrict__ Ap, const float4* __restrict__ Bp,
                        const float* __restrict__ bias, float* __restrict__ C,
                        int Mt, int Nt, int K, int mode,
                        const float* __restrict__ ct, const float* __restrict__ st)
{
    extern __shared__ char smx[];
    const uint32_t sb = smem_u32(smx);
    const int t    = threadIdx.x;
    const int wid  = t >> 5;
    const int lane = t & 31;
    const int g    = lane >> 2;
    const int tg   = lane & 3;
    const int wm   = wid & 1;     // m half (64 rows)
    const int wn   = wid >> 1;    // n quarter (64 cols)
    const int rowBase = blockIdx.y * 128;
    const int colBase = blockIdx.x * 256;

    float acc[4][8][4];
    #pragma unroll
    for (int mi = 0; mi < 4; mi++)
        #pragma unroll
        for (int ni = 0; ni < 8; ni++)
            #pragma unroll
            for (int r = 0; r < 4; r++) acc[mi][ni][r] = 0.0f;

    const int NK = K / 16;

    auto issue = [&](int kt) {
        const uint32_t base = sb + (kt % 3) * STAGE_BYTES;
        #pragma unroll
        for (int i = 0; i < 6; i++) {
            const int u = t + (i << 8);
            if (u < 512) {
                const int tg4 = u >> 7, mm = u & 127;
                cp16s(base + (tg4 * 130 + mm) * 16,
                      Ap + ((size_t)(kt * 4 + tg4) * Mt + rowBase + mm));
            } else {
                const int v = u - 512;
                const int tg4 = v >> 8, nn = v & 255;
                cp16s(base + (ACELLS + tg4 * 258 + nn) * 16,
                      Bp + ((size_t)(kt * 4 + tg4) * Nt + colBase + nn));
            }
        }
        cp_commit();
    };

    issue(0);
    issue(1);

    for (int kt = 0; kt < NK; kt++) {
        cp_wait<1>();
        __syncthreads();
        if (kt + 2 < NK) issue(kt + 2);

        const float* Asl = (const float*)(smx + (kt % 3) * STAGE_BYTES);
        const float* Bsl = Asl + ACELLS * 4;

        float4 A0[4], A1[4];
        #pragma unroll
        for (int mi = 0; mi < 4; mi++) {
            const int mr = wm * 64 + mi * 16 + g;
            A0[mi] = *(const float4*)&Asl[(tg * 130 + mr) * 4];
            A1[mi] = *(const float4*)&Asl[(tg * 130 + mr + 8) * 4];
        }
        #pragma unroll
        for (int half = 0; half < 2; half++) {
            float4 Bv[4];
            #pragma unroll
            for (int nj = 0; nj < 4; nj++)
                Bv[nj] = *(const float4*)&Bsl[(tg * 258 + wn * 64 + (half * 4 + nj) * 8 + g) * 4];
            #pragma unroll
            for (int mi = 0; mi < 4; mi++)
                #pragma unroll
                for (int nj = 0; nj < 4; nj++) {
                    float* a = acc[mi][half * 4 + nj];
                    mma_tf32(a, FU(A0[mi].x), FU(A1[mi].x), FU(A0[mi].y), FU(A1[mi].y),
                             FU(Bv[nj].x), FU(Bv[nj].y));
                    mma_tf32(a, FU(A0[mi].z), FU(A1[mi].z), FU(A0[mi].w), FU(A1[mi].w),
                             FU(Bv[nj].z), FU(Bv[nj].w));
                }
        }
        // no bottom barrier: with 3 stages, issue(kt+2) targets stage (kt-1)%3,
        // whose readers all passed this iteration's top barrier.
    }
    cp_wait<0>();

    // ---- epilogue: bias (+fused rope + tf32 rounding when mode==1) ----
    #pragma unroll
    for (int mi = 0; mi < 4; mi++) {
        const int r0 = rowBase + wm * 64 + mi * 16 + g;
        const int r1 = r0 + 8;
        #pragma unroll
        for (int ni = 0; ni < 8; ni++) {
            const int c = colBase + wn * 64 + ni * 8 + tg * 2;
            const float2 b2 = *(const float2*)&bias[c];
            float v0 = acc[mi][ni][0] + b2.x;
            float v1 = acc[mi][ni][1] + b2.y;
            float v2 = acc[mi][ni][2] + b2.x;
            float v3 = acc[mi][ni][3] + b2.y;
            if (mode == 1) {
                const int sect = c >> 11;
                if (sect < 2) {
                    const int pj = (c & 127) >> 1;
                    const float c0 = ct[(r0 & (TT - 1)) * 64 + pj];
                    const float s0 = st[(r0 & (TT - 1)) * 64 + pj];
                    const float c1 = ct[(r1 & (TT - 1)) * 64 + pj];
                    const float s1 = st[(r1 & (TT - 1)) * 64 + pj];
                    float e0 = v0 * c0 - v1 * s0, o0 = v0 * s0 + v1 * c0;
                    float e1 = v2 * c1 - v3 * s1, o1 = v2 * s1 + v3 * c1;
                    v0 = e0; v1 = o0; v2 = e1; v3 = o1;
                }
                v0 = tfr(v0); v1 = tfr(v1); v2 = tfr(v2); v3 = tfr(v3);
            }
            *(float2*)&C[(size_t)r0 * Nt + c] = make_float2(v0, v1);
            *(float2*)&C[(size_t)r1 * Nt + c] = make_float2(v2, v3);
        }
    }
}

// ---------------- RoPE tables ----------------
__global__ void freq_kernel(float* __restrict__ inv)
{
    int p = threadIdx.x;
    if (p < 64) inv[p] = (float)pow(10000.0, -(double)p / 64.0);
}

__global__ void trig_kernel(const float* __restrict__ inv,
                            float* __restrict__ ct, float* __restrict__ st)
{
    int idx = blockIdx.x * blockDim.x + threadIdx.x;
    if (idx >= TT * 64) return;
    int tpos = idx >> 6;
    int p    = idx & 63;
    float ang = (float)tpos * inv[p];
    float s, c;
    sincosf(ang, &s, &c);
    ct[idx] = c;
    st[idx] = s;
}

// ---------------- Flash attention (tf32 tensor cores, causal) ----------------
#define LDKK 132
#define LDVV 136
#define LDPK 132
#define ATT_SMEM ((2*64*LDKK + 2*64*LDVV + 128*LDPK) * 4)   // 200 KB

__global__ __launch_bounds__(256, 1)
void attn_mma_kernel()
{
    extern __shared__ float sm[];
    float* Ks = sm;                                  // [2][64][LDKK]
    float* Vs = Ks + 2 * 64 * LDKK;                  // [2][64][LDVV]
    float* Ps = Vs + 2 * 64 * LDVV;                  // [128][LDPK] (also Q staging)

    const int t    = threadIdx.x;
    const int lane = t & 31;
    const int w    = t >> 5;
    const int g    = lane >> 2;
    const int tg   = lane & 3;
    const int bh = blockIdx.y;
    const int b  = bh >> 4;
    const int h  = bh & 15;
    const int qt = (int)gridDim.x - 1 - (int)blockIdx.x;
    const int qbase = qt * 128;
    const size_t rowbase = (size_t)b * TT;
    const int hoff = h * DK;
    const float scale = 0.08838834764831845f;

    for (int u = t; u < 128 * 32; u += 256) {
        int qi = u >> 5;
        int c  = u & 31;
        float4 v = *(const float4*)&g_kqv[(rowbase + qbase + qi) * N3 + DD + hoff + c * 4];
        *(float4*)&Ps[qi * LDPK + c * 4] = v;
    }
    __syncthreads();
    const int qr = w * 16 + g;
    uint32_t qf[16][4];
    #pragma unroll
    for (int ks = 0; ks < 16; ks++) {
        qf[ks][0] = *(const uint32_t*)&Ps[qr * LDPK + ks * 8 + tg];
        qf[ks][1] = *(const uint32_t*)&Ps[(qr + 8) * LDPK + ks * 8 + tg];
        qf[ks][2] = *(const uint32_t*)&Ps[qr * LDPK + ks * 8 + tg + 4];
        qf[ks][3] = *(const uint32_t*)&Ps[(qr + 8) * LDPK + ks * 8 + tg + 4];
    }
    __syncthreads();

    float oacc[16][4];
    #pragma unroll
    for (int ni = 0; ni < 16; ni++)
        #pragma unroll
        for (int r = 0; r < 4; r++) oacc[ni][r] = 0.0f;
    float m0 = -1e30f, m1 = -1e30f, l0 = 0.0f, l1 = 0.0f;

    auto issue_tile = [&](int kt) {
        const int s = kt & 1;
        #pragma unroll
        for (int i = 0; i < 8; i++) {
            int u = t + i * 256;
            int r = u >> 5;
            int c = u & 31;
            const size_t grow = (rowbase + (size_t)kt * 64 + r) * N3;
            cp16(&Ks[s * 64 * LDKK + r * LDKK + c * 4], &g_kqv[grow + hoff + c * 4]);
            cp16(&Vs[s * 64 * LDVV + r * LDVV + c * 4], &g_kqv[grow + 2 * DD + hoff + c * 4]);
        }
        cp_commit();
    };

    const int nkt = 2 * qt + 2;
    issue_tile(0);

    for (int kt = 0; kt < nkt; kt++) {
        const int s = kt & 1;
        __syncthreads();
        if (kt + 1 < nkt) issue_tile(kt + 1);
        cp_wait<1>();
        __syncthreads();

        float sacc[8][4];
        #pragma unroll
        for (int ni = 0; ni < 8; ni++)
            #pragma unroll
            for (int r = 0; r < 4; r++) sacc[ni][r] = 0.0f;

        const float* Kb = Ks + s * 64 * LDKK;
        #pragma unroll
        for (int ks = 0; ks < 16; ks++) {
            #pragma unroll
            for (int ni = 0; ni < 8; ni++) {
                uint32_t b0 = *(const uint32_t*)&Kb[(ni * 8 + g) * LDKK + ks * 8 + tg];
                uint32_t b1 = *(const uint32_t*)&Kb[(ni * 8 + g) * LDKK + ks * 8 + tg + 4];
                mma_tf32(sacc[ni], qf[ks][0], qf[ks][1], qf[ks][2], qf[ks][3], b0, b1);
            }
        }

        const int r0 = qbase + w * 16 + g;
        const int r1 = r0 + 8;
        const int kb = kt * 64;
        float rm0 = -1e30f, rm1 = -1e30f;
        #pragma unroll
        for (int ni = 0; ni < 8; ni++) {
            const int c0 = kb + ni * 8 + 2 * tg;
            float v0 = sacc[ni][0] * scale; if (c0     > r0) v0 = -1e30f;
            float v1 = sacc[ni][1] * scale; if (c0 + 1 > r0) v1 = -1e30f;
            float v2 = sacc[ni][2] * scale; if (c0     > r1) v2 = -1e30f;
            float v3 = sacc[ni][3] * scale; if (c0 + 1 > r1) v3 = -1e30f;
            sacc[ni][0] = v0; sacc[ni][1] = v1; sacc[ni][2] = v2; sacc[ni][3] = v3;
            rm0 = fmaxf(rm0, fmaxf(v0, v1));
            rm1 = fmaxf(rm1, fmaxf(v2, v3));
        }
        rm0 = fmaxf(rm0, __shfl_xor_sync(0xffffffffu, rm0, 1));
        rm0 = fmaxf(rm0, __shfl_xor_sync(0xffffffffu, rm0, 2));
        rm1 = fmaxf(rm1, __shfl_xor_sync(0xffffffffu, rm1, 1));
        rm1 = fmaxf(rm1, __shfl_xor_sync(0xffffffffu, rm1, 2));

        const float mn0 = fmaxf(m0, rm0);
        const float mn1 = fmaxf(m1, rm1);
        const float f0 = __expf(m0 - mn0);
        const float f1 = __expf(m1 - mn1);
        m0 = mn0; m1 = mn1;

        float ps0 = 0.0f, ps1 = 0.0f;
        #pragma unroll
        for (int ni = 0; ni < 8; ni++) {
            float p0 = __expf(sacc[ni][0] - mn0);
            float p1 = __expf(sacc[ni][1] - mn0);
            float p2 = __expf(sacc[ni][2] - mn1);
            float p3 = __expf(sacc[ni][3] - mn1);
            sacc[ni][0] = p0; sacc[ni][1] = p1; sacc[ni][2] = p2; sacc[ni][3] = p3;
            ps0 += p0 + p1;
            ps1 += p2 + p3;
        }
        ps0 += __shfl_xor_sync(0xffffffffu, ps0, 1);
        ps0 += __shfl_xor_sync(0xffffffffu, ps0, 2);
        ps1 += __shfl_xor_sync(0xffffffffu, ps1, 1);
        ps1 += __shfl_xor_sync(0xffffffffu, ps1, 2);
        l0 = l0 * f0 + ps0;
        l1 = l1 * f1 + ps1;

        #pragma unroll
        for (int ni = 0; ni < 16; ni++) {
            oacc[ni][0] *= f0; oacc[ni][1] *= f0;
            oacc[ni][2] *= f1; oacc[ni][3] *= f1;
        }

        const int pq = w * 16 + g;
        #pragma unroll
        for (int ni = 0; ni < 8; ni++) {
            *(float2*)&Ps[pq * LDPK + ni * 8 + 2 * tg]       = make_float2(sacc[ni][0], sacc[ni][1]);
            *(float2*)&Ps[(pq + 8) * LDPK + ni * 8 + 2 * tg] = make_float2(sacc[ni][2], sacc[ni][3]);
        }
        __syncthreads();

        // ---- O += P @ V  (single tf32 pass) ----
        const float* Vb = Vs + s * 64 * LDVV;
        #pragma unroll
        for (int ks2 = 0; ks2 < 8; ks2++) {
            uint32_t h0 = f2tf(Ps[pq * LDPK + ks2 * 8 + tg]);
            uint32_t h1 = f2tf(Ps[(pq + 8) * LDPK + ks2 * 8 + tg]);
            uint32_t h2 = f2tf(Ps[pq * LDPK + ks2 * 8 + tg + 4]);
            uint32_t h3 = f2tf(Ps[(pq + 8) * LDPK + ks2 * 8 + tg + 4]);
            #pragma unroll
            for (int ni = 0; ni < 16; ni++) {
                uint32_t b0 = *(const uint32_t*)&Vb[(ks2 * 8 + tg) * LDVV + ni * 8 + g];
                uint32_t b1 = *(const uint32_t*)&Vb[(ks2 * 8 + tg + 4) * LDVV + ni * 8 + g];
                mma_tf32(oacc[ni], h0, h1, h2, h3, b0, b1);
            }
        }
    }

    // ---- epilogue: O / l -> g_attn fp32 ----
    const float il0 = 1.0f / l0;
    const float il1 = 1.0f / l1;
    const size_t row0 = rowbase + qbase + w * 16 + g;
    #pragma unroll
    for (int ni = 0; ni < 16; ni++) {
        const int col = hoff + ni * 8 + 2 * tg;
        *(float2*)&g_attn[row0 * DD + col] =
            make_float2(oacc[ni][0] * il0, oacc[ni][1] * il0);
        *(float2*)&g_attn[(row0 + 8) * DD + col] =
            make_float2(oacc[ni][2] * il1, oacc[ni][3] * il1);
    }
}

// ---------------- launch ----------------
extern "C" void kernel_launch(void* const* d_in, const int* in_sizes, int n_in,
                              void* d_out, int out_size)
{
    const float* x    = (const float*)d_in[0];
    const float* Wkqv = (const float*)d_in[1];
    const float* bkqv = (const float*)d_in[2];
    const float* Wo   = (const float*)d_in[3];
    const float* bo   = (const float*)d_in[4];
    float* out = (float*)d_out;

    float *kqv, *attn, *xp, *wkp, *wop, *ap, *inv, *ct, *st;
    cudaGetSymbolAddress((void**)&kqv, g_kqv);
    cudaGetSymbolAddress((void**)&attn, g_attn);
    cudaGetSymbolAddress((void**)&xp,  g_xp);
    cudaGetSymbolAddress((void**)&wkp, g_wkp);
    cudaGetSymbolAddress((void**)&wop, g_wop);
    cudaGetSymbolAddress((void**)&ap,  g_ap);
    cudaGetSymbolAddress((void**)&inv, g_inv);
    cudaGetSymbolAddress((void**)&ct,  g_cos);
    cudaGetSymbolAddress((void**)&st,  g_sin);

    cudaFuncSetAttribute(gemm_packed_kernel, cudaFuncAttributeMaxDynamicSharedMemorySize, GEMM_SMEM);
    cudaFuncSetAttribute(attn_mma_kernel,    cudaFuncAttributeMaxDynamicSharedMemorySize, ATT_SMEM);

    // 0) rope tables + pack operands (tf32 rna rounding folded in)
    freq_kernel<<<1, 64>>>(inv);
    trig_kernel<<<(TT * 64) / 256, 256>>>(inv, ct, st);
    packA_kernel<<<dim3(DD / 64, MROWS / 32), 256>>>(x, (float4*)xp, MROWS, DD);
    packB_kernel<<<(DD / 4 * N3 + 255) / 256, 256>>>(Wkqv, (float4*)wkp, DD, N3);
    packB_kernel<<<(DD / 4 * DD + 255) / 256, 256>>>(Wo, (float4*)wop, DD, DD);

    // 1) kqv = x @ Wkqv + bkqv, fused rope + tf32 rounding
    gemm_packed_kernel<<<dim3(N3 / 256, MROWS / 128), 256, GEMM_SMEM>>>(
        (const float4*)xp, (const float4*)wkp, bkqv, kqv, MROWS, N3, DD, 1, ct, st);

    // 2) causal flash attention -> g_attn
    attn_mma_kernel<<<dim3(TT / 128, BB * HH), 256, ATT_SMEM>>>();

    // 3) pack attention output, then out = attn @ Wo + bo
    packA_kernel<<<dim3(DD / 64, MROWS / 32), 256>>>(attn, (float4*)ap, MROWS, DD);
    gemm_packed_kernel<<<dim3(DD / 256, MROWS / 128), 256, GEMM_SMEM>>>(
        (const float4*)ap, (const float4*)wop, bo, out, MROWS, DD, DD, 0, ct, st);
}

// round 7
// speedup vs baseline: 1.1079x; 1.1079x over previous
#include <cuda_runtime.h>
#include <math.h>
#include <stdint.h>

#define BB    2
#define TT    2048
#define DD    2048
#define HH    16
#define DK    128
#define N3    (3*DD)
#define MROWS (BB*TT)   // 4096

// ---------------- scratch (device globals; no allocation allowed) ----------------
__device__ float g_kqv[(size_t)MROWS * N3];    // fp32 k|q|v (tf32-rounded, rope applied)
__device__ float g_attn[(size_t)MROWS * DD];   // attention output fp32
__device__ float g_xp[(size_t)MROWS * DD];     // x packed (tf32)   [ck][M] float4 cells
__device__ float g_wkp[(size_t)DD * N3];       // Wkqv packed       [ck][N] float4 cells
__device__ float g_wop[(size_t)DD * DD];       // Wo packed
__device__ float g_ap[(size_t)MROWS * DD];     // attn packed
__device__ float g_inv[64];
__device__ float g_cos[TT * 64];
__device__ float g_sin[TT * 64];

// ---------------- PTX helpers ----------------
__device__ __forceinline__ uint32_t smem_u32(const void* p) {
    return (uint32_t)__cvta_generic_to_shared(p);
}
__device__ __forceinline__ void cp16s(uint32_t dst, const void* src) {
    asm volatile("cp.async.cg.shared.global [%0], [%1], 16;\n" :: "r"(dst), "l"(src));
}
__device__ __forceinline__ void cp16(void* dst, const void* src) {
    asm volatile("cp.async.cg.shared.global [%0], [%1], 16;\n"
                 :: "r"(smem_u32(dst)), "l"(src));
}
__device__ __forceinline__ void cp_commit() {
    asm volatile("cp.async.commit_group;\n");
}
template<int N>
__device__ __forceinline__ void cp_wait() {
    asm volatile("cp.async.wait_group %0;\n" :: "n"(N));
}
__device__ __forceinline__ uint32_t f2tf(float f) {
    uint32_t r;
    asm("cvt.rna.tf32.f32 %0, %1;" : "=r"(r) : "f"(f));
    return r;
}
__device__ __forceinline__ float tfr(float f) {
    return __uint_as_float(f2tf(f));
}
__device__ __forceinline__ void mma_tf32(float c[4],
                                         uint32_t a0, uint32_t a1, uint32_t a2, uint32_t a3,
                                         uint32_t b0, uint32_t b1) {
    asm volatile(
        "mma.sync.aligned.m16n8k8.row.col.f32.tf32.tf32.f32 "
        "{%0,%1,%2,%3}, {%4,%5,%6,%7}, {%8,%9}, {%0,%1,%2,%3};\n"
        : "+f"(c[0]), "+f"(c[1]), "+f"(c[2]), "+f"(c[3])
        : "r"(a0), "r"(a1), "r"(a2), "r"(a3), "r"(b0), "r"(b1));
}
#define FU(x) __float_as_uint(x)

// ---------------- pack kernels: fragment-order gmem layout ----------------
// Cell (ck, i), ck = kg*4+tg, holds (X[i][kb], X[i][kb+4], X[i][kb+8], X[i][kb+12]),
// kb = kg*16+tg, as float4 at out[ck*Len + i]. Values tf32(rna)-rounded.

__global__ void packA_kernel(const float* __restrict__ in, float4* __restrict__ out,
                             int Mt, int K)
{
    __shared__ float tile[32][65];
    const int k0 = blockIdx.x * 64;
    const int m0 = blockIdx.y * 32;
    const int t  = threadIdx.x;
    #pragma unroll
    for (int i = 0; i < 2; i++) {
        int u = t + (i << 8);
        int m = u >> 4;
        int kc = u & 15;
        float4 v = *(const float4*)&in[(size_t)(m0 + m) * K + k0 + kc * 4];
        tile[m][kc * 4 + 0] = v.x;
        tile[m][kc * 4 + 1] = v.y;
        tile[m][kc * 4 + 2] = v.z;
        tile[m][kc * 4 + 3] = v.w;
    }
    __syncthreads();
    #pragma unroll
    for (int i = 0; i < 2; i++) {
        int u  = t + (i << 8);
        int ck = u >> 5;
        int m  = u & 31;
        int kg = ck >> 2, tg = ck & 3;
        int kb = kg * 16 + tg;
        float4 v;
        v.x = tfr(tile[m][kb]);
        v.y = tfr(tile[m][kb + 4]);
        v.z = tfr(tile[m][kb + 8]);
        v.w = tfr(tile[m][kb + 12]);
        out[(size_t)((k0 / 16 + kg) * 4 + tg) * Mt + m0 + m] = v;
    }
}

__global__ void packB_kernel(const float* __restrict__ W, float4* __restrict__ out,
                             int K, int N)
{
    int idx = blockIdx.x * 256 + threadIdx.x;
    int total = (K / 4) * N;
    if (idx >= total) return;
    int ck = idx / N;
    int n  = idx - ck * N;
    int kg = ck >> 2, tg = ck & 3;
    int kb = kg * 16 + tg;
    float4 v;
    v.x = tfr(W[(size_t)kb * N + n]);
    v.y = tfr(W[(size_t)(kb + 4) * N + n]);
    v.z = tfr(W[(size_t)(kb + 8) * N + n]);
    v.w = tfr(W[(size_t)(kb + 12) * N + n]);
    out[(size_t)ck * N + n] = v;
}

// ---------------- packed TF32 GEMM: CTA 128x128, warp 64x32, BK=16, 3 stages ----------------
// Stage cells (16B): A 4*130 + B 4*130, stride 130 => conflict-free LDS.128.
#define STAGE_BYTES 8320                      // 4*130*16 (A half); B half same size
#define GEMM_SMEM   (6 * STAGE_BYTES)         // 49920

__global__ __launch_bounds__(256, 2)
void gemm_packed_kernel(const float4* __restrict__ Ap, const float4* __restrict__ Bp,
                        const float* __restrict__ bias, float* __restrict__ C,
                        int Mt, int Nt, int K, int mode,
                        const float* __restrict__ ct, const float* __restrict__ st)
{
    extern __shared__ char smx[];
    const uint32_t sb = smem_u32(smx);
    const int t    = threadIdx.x;
    const int wid  = t >> 5;
    const int lane = t & 31;
    const int g    = lane >> 2;
    const int tg   = lane & 3;
    const int wm   = wid & 1;
    const int wn   = wid >> 1;
    const int rowBase = blockIdx.y * 128;
    const int colBase = blockIdx.x * 128;

    float acc[4][4][4];
    #pragma unroll
    for (int mi = 0; mi < 4; mi++)
        #pragma unroll
        for (int ni = 0; ni < 4; ni++)
            #pragma unroll
            for (int r = 0; r < 4; r++) acc[mi][ni][r] = 0.0f;

    const int NK = K / 16;

    auto issue = [&](int kt) {
        const int s = kt % 3;
        #pragma unroll
        for (int i = 0; i < 4; i++) {
            const int u   = t + (i << 8);            // 0..1023
            const int tg4 = (u >> 7) & 3;
            const int mm  = u & 127;
            if (u < 512) {
                uint32_t dst = sb + s * STAGE_BYTES + (tg4 * 130 + mm) * 16;
                cp16s(dst, Ap + ((size_t)(kt * 4 + tg4) * Mt + rowBase + mm));
            } else {
                uint32_t dst = sb + 3 * STAGE_BYTES + s * STAGE_BYTES + (tg4 * 130 + mm) * 16;
                cp16s(dst, Bp + ((size_t)(kt * 4 + tg4) * Nt + colBase + mm));
            }
        }
        cp_commit();
    };

    issue(0);
    issue(1);

    for (int kt = 0; kt < NK; kt++) {
        cp_wait<1>();
        __syncthreads();
        if (kt + 2 < NK) issue(kt + 2);

        const float* Asl = (const float*)(smx + (kt % 3) * STAGE_BYTES);
        const float* Bsl = (const float*)(smx + 3 * STAGE_BYTES + (kt % 3) * STAGE_BYTES);

        float4 A0[4], A1[4], Bv[4];
        #pragma unroll
        for (int mi = 0; mi < 4; mi++) {
            const int mr = wm * 64 + mi * 16 + g;
            A0[mi] = *(const float4*)&Asl[(tg * 130 + mr) * 4];
            A1[mi] = *(const float4*)&Asl[(tg * 130 + mr + 8) * 4];
        }
        #pragma unroll
        for (int ni = 0; ni < 4; ni++)
            Bv[ni] = *(const float4*)&Bsl[(tg * 130 + wn * 32 + ni * 8 + g) * 4];

        #pragma unroll
        for (int mi = 0; mi < 4; mi++)
            #pragma unroll
            for (int ni = 0; ni < 4; ni++) {
                mma_tf32(acc[mi][ni], FU(A0[mi].x), FU(A1[mi].x), FU(A0[mi].y), FU(A1[mi].y),
                         FU(Bv[ni].x), FU(Bv[ni].y));
                mma_tf32(acc[mi][ni], FU(A0[mi].z), FU(A1[mi].z), FU(A0[mi].w), FU(A1[mi].w),
                         FU(Bv[ni].z), FU(Bv[ni].w));
            }
        // no bottom barrier: with 3 stages, issue(kt+2) targets stage (kt-1)%3,
        // whose readers all passed this iteration's top barrier.
    }
    cp_wait<0>();

    // ---- epilogue: bias (+fused rope + tf32 rounding when mode==1) ----
    #pragma unroll
    for (int mi = 0; mi < 4; mi++) {
        const int r0 = rowBase + wm * 64 + mi * 16 + g;
        const int r1 = r0 + 8;
        #pragma unroll
        for (int ni = 0; ni < 4; ni++) {
            const int c = colBase + wn * 32 + ni * 8 + tg * 2;
            const float2 b2 = *(const float2*)&bias[c];
            float v0 = acc[mi][ni][0] + b2.x;
            float v1 = acc[mi][ni][1] + b2.y;
            float v2 = acc[mi][ni][2] + b2.x;
            float v3 = acc[mi][ni][3] + b2.y;
            if (mode == 1) {
                const int sect = c >> 11;
                if (sect < 2) {
                    const int pj = (c & 127) >> 1;
                    const float c0 = ct[(r0 & (TT - 1)) * 64 + pj];
                    const float s0 = st[(r0 & (TT - 1)) * 64 + pj];
                    const float c1 = ct[(r1 & (TT - 1)) * 64 + pj];
                    const float s1 = st[(r1 & (TT - 1)) * 64 + pj];
                    float e0 = v0 * c0 - v1 * s0, o0 = v0 * s0 + v1 * c0;
                    float e1 = v2 * c1 - v3 * s1, o1 = v2 * s1 + v3 * c1;
                    v0 = e0; v1 = o0; v2 = e1; v3 = o1;
                }
                v0 = tfr(v0); v1 = tfr(v1); v2 = tfr(v2); v3 = tfr(v3);
            }
            *(float2*)&C[(size_t)r0 * Nt + c] = make_float2(v0, v1);
            *(float2*)&C[(size_t)r1 * Nt + c] = make_float2(v2, v3);
        }
    }
}

// ---------------- RoPE tables ----------------
__global__ void freq_kernel(float* __restrict__ inv)
{
    int p = threadIdx.x;
    if (p < 64) inv[p] = (float)pow(10000.0, -(double)p / 64.0);
}

__global__ void trig_kernel(const float* __restrict__ inv,
                            float* __restrict__ ct, float* __restrict__ st)
{
    int idx = blockIdx.x * blockDim.x + threadIdx.x;
    if (idx >= TT * 64) return;
    int tpos = idx >> 6;
    int p    = idx & 63;
    float ang = (float)tpos * inv[p];
    float s, c;
    sincosf(ang, &s, &c);
    ct[idx] = c;
    st[idx] = s;
}

// ---------------- Flash attention (tf32 tensor cores, causal) ----------------
#define LDKK 132
#define LDVV 136
#define LDPK 132
#define ATT_SMEM ((2*64*LDKK + 2*64*LDVV + 128*LDPK) * 4)   // 200 KB

__global__ __launch_bounds__(256, 1)
void attn_mma_kernel()
{
    extern __shared__ float sm[];
    float* Ks = sm;                                  // [2][64][LDKK]
    float* Vs = Ks + 2 * 64 * LDKK;                  // [2][64][LDVV]
    float* Ps = Vs + 2 * 64 * LDVV;                  // [128][LDPK] (also Q staging)

    const int t    = threadIdx.x;
    const int lane = t & 31;
    const int w    = t >> 5;
    const int g    = lane >> 2;
    const int tg   = lane & 3;
    const int bh = blockIdx.y;
    const int b  = bh >> 4;
    const int h  = bh & 15;
    const int qt = (int)gridDim.x - 1 - (int)blockIdx.x;
    const int qbase = qt * 128;
    const size_t rowbase = (size_t)b * TT;
    const int hoff = h * DK;
    const float scale = 0.08838834764831845f;

    for (int u = t; u < 128 * 32; u += 256) {
        int qi = u >> 5;
        int c  = u & 31;
        float4 v = *(const float4*)&g_kqv[(rowbase + qbase + qi) * N3 + DD + hoff + c * 4];
        *(float4*)&Ps[qi * LDPK + c * 4] = v;
    }
    __syncthreads();
    const int qr = w * 16 + g;
    uint32_t qf[16][4];
    #pragma unroll
    for (int ks = 0; ks < 16; ks++) {
        qf[ks][0] = *(const uint32_t*)&Ps[qr * LDPK + ks * 8 + tg];
        qf[ks][1] = *(const uint32_t*)&Ps[(qr + 8) * LDPK + ks * 8 + tg];
        qf[ks][2] = *(const uint32_t*)&Ps[qr * LDPK + ks * 8 + tg + 4];
        qf[ks][3] = *(const uint32_t*)&Ps[(qr + 8) * LDPK + ks * 8 + tg + 4];
    }
    __syncthreads();

    float oacc[16][4];
    #pragma unroll
    for (int ni = 0; ni < 16; ni++)
        #pragma unroll
        for (int r = 0; r < 4; r++) oacc[ni][r] = 0.0f;
    float m0 = -1e30f, m1 = -1e30f, l0 = 0.0f, l1 = 0.0f;

    auto issue_tile = [&](int kt) {
        const int s = kt & 1;
        #pragma unroll
        for (int i = 0; i < 8; i++) {
            int u = t + i * 256;
            int r = u >> 5;
            int c = u & 31;
            const size_t grow = (rowbase + (size_t)kt * 64 + r) * N3;
            cp16(&Ks[s * 64 * LDKK + r * LDKK + c * 4], &g_kqv[grow + hoff + c * 4]);
            cp16(&Vs[s * 64 * LDVV + r * LDVV + c * 4], &g_kqv[grow + 2 * DD + hoff + c * 4]);
        }
        cp_commit();
    };

    const int nkt = 2 * qt + 2;
    issue_tile(0);

    for (int kt = 0; kt < nkt; kt++) {
        const int s = kt & 1;
        __syncthreads();
        if (kt + 1 < nkt) issue_tile(kt + 1);
        cp_wait<1>();
        __syncthreads();

        float sacc[8][4];
        #pragma unroll
        for (int ni = 0; ni < 8; ni++)
            #pragma unroll
            for (int r = 0; r < 4; r++) sacc[ni][r] = 0.0f;

        const float* Kb = Ks + s * 64 * LDKK;
        #pragma unroll
        for (int ks = 0; ks < 16; ks++) {
            #pragma unroll
            for (int ni = 0; ni < 8; ni++) {
                uint32_t b0 = *(const uint32_t*)&Kb[(ni * 8 + g) * LDKK + ks * 8 + tg];
                uint32_t b1 = *(const uint32_t*)&Kb[(ni * 8 + g) * LDKK + ks * 8 + tg + 4];
                mma_tf32(sacc[ni], qf[ks][0], qf[ks][1], qf[ks][2], qf[ks][3], b0, b1);
            }
        }

        const int r0 = qbase + w * 16 + g;
        const int r1 = r0 + 8;
        const int kb = kt * 64;
        float rm0 = -1e30f, rm1 = -1e30f;
        #pragma unroll
        for (int ni = 0; ni < 8; ni++) {
            const int c0 = kb + ni * 8 + 2 * tg;
            float v0 = sacc[ni][0] * scale; if (c0     > r0) v0 = -1e30f;
            float v1 = sacc[ni][1] * scale; if (c0 + 1 > r0) v1 = -1e30f;
            float v2 = sacc[ni][2] * scale; if (c0     > r1) v2 = -1e30f;
            float v3 = sacc[ni][3] * scale; if (c0 + 1 > r1) v3 = -1e30f;
            sacc[ni][0] = v0; sacc[ni][1] = v1; sacc[ni][2] = v2; sacc[ni][3] = v3;
            rm0 = fmaxf(rm0, fmaxf(v0, v1));
            rm1 = fmaxf(rm1, fmaxf(v2, v3));
        }
        rm0 = fmaxf(rm0, __shfl_xor_sync(0xffffffffu, rm0, 1));
        rm0 = fmaxf(rm0, __shfl_xor_sync(0xffffffffu, rm0, 2));
        rm1 = fmaxf(rm1, __shfl_xor_sync(0xffffffffu, rm1, 1));
        rm1 = fmaxf(rm1, __shfl_xor_sync(0xffffffffu, rm1, 2));

        const float mn0 = fmaxf(m0, rm0);
        const float mn1 = fmaxf(m1, rm1);
        const float f0 = __expf(m0 - mn0);
        const float f1 = __expf(m1 - mn1);
        m0 = mn0; m1 = mn1;

        float ps0 = 0.0f, ps1 = 0.0f;
        #pragma unroll
        for (int ni = 0; ni < 8; ni++) {
            float p0 = __expf(sacc[ni][0] - mn0);
            float p1 = __expf(sacc[ni][1] - mn0);
            float p2 = __expf(sacc[ni][2] - mn1);
            float p3 = __expf(sacc[ni][3] - mn1);
            sacc[ni][0] = p0; sacc[ni][1] = p1; sacc[ni][2] = p2; sacc[ni][3] = p3;
            ps0 += p0 + p1;
            ps1 += p2 + p3;
        }
        ps0 += __shfl_xor_sync(0xffffffffu, ps0, 1);
        ps0 += __shfl_xor_sync(0xffffffffu, ps0, 2);
        ps1 += __shfl_xor_sync(0xffffffffu, ps1, 1);
        ps1 += __shfl_xor_sync(0xffffffffu, ps1, 2);
        l0 = l0 * f0 + ps0;
        l1 = l1 * f1 + ps1;

        #pragma unroll
        for (int ni = 0; ni < 16; ni++) {
            oacc[ni][0] *= f0; oacc[ni][1] *= f0;
            oacc[ni][2] *= f1; oacc[ni][3] *= f1;
        }

        const int pq = w * 16 + g;
        #pragma unroll
        for (int ni = 0; ni < 8; ni++) {
            *(float2*)&Ps[pq * LDPK + ni * 8 + 2 * tg]       = make_float2(sacc[ni][0], sacc[ni][1]);
            *(float2*)&Ps[(pq + 8) * LDPK + ni * 8 + 2 * tg] = make_float2(sacc[ni][2], sacc[ni][3]);
        }
        __syncthreads();

        // ---- O += P @ V  (single tf32 pass) ----
        const float* Vb = Vs + s * 64 * LDVV;
        #pragma unroll
        for (int ks2 = 0; ks2 < 8; ks2++) {
            uint32_t h0 = f2tf(Ps[pq * LDPK + ks2 * 8 + tg]);
            uint32_t h1 = f2tf(Ps[(pq + 8) * LDPK + ks2 * 8 + tg]);
            uint32_t h2 = f2tf(Ps[pq * LDPK + ks2 * 8 + tg + 4]);
            uint32_t h3 = f2tf(Ps[(pq + 8) * LDPK + ks2 * 8 + tg + 4]);
            #pragma unroll
            for (int ni = 0; ni < 16; ni++) {
                uint32_t b0 = *(const uint32_t*)&Vb[(ks2 * 8 + tg) * LDVV + ni * 8 + g];
                uint32_t b1 = *(const uint32_t*)&Vb[(ks2 * 8 + tg + 4) * LDVV + ni * 8 + g];
                mma_tf32(oacc[ni], h0, h1, h2, h3, b0, b1);
            }
        }
    }

    // ---- epilogue: O / l -> g_attn fp32 ----
    const float il0 = 1.0f / l0;
    const float il1 = 1.0f / l1;
    const size_t row0 = rowbase + qbase + w * 16 + g;
    #pragma unroll
    for (int ni = 0; ni < 16; ni++) {
        const int col = hoff + ni * 8 + 2 * tg;
        *(float2*)&g_attn[row0 * DD + col] =
            make_float2(oacc[ni][0] * il0, oacc[ni][1] * il0);
        *(float2*)&g_attn[(row0 + 8) * DD + col] =
            make_float2(oacc[ni][2] * il1, oacc[ni][3] * il1);
    }
}

// ---------------- launch ----------------
extern "C" void kernel_launch(void* const* d_in, const int* in_sizes, int n_in,
                              void* d_out, int out_size)
{
    const float* x    = (const float*)d_in[0];
    const float* Wkqv = (const float*)d_in[1];
    const float* bkqv = (const float*)d_in[2];
    const float* Wo   = (const float*)d_in[3];
    const float* bo   = (const float*)d_in[4];
    float* out = (float*)d_out;

    float *kqv, *attn, *xp, *wkp, *wop, *ap, *inv, *ct, *st;
    cudaGetSymbolAddress((void**)&kqv, g_kqv);
    cudaGetSymbolAddress((void**)&attn, g_attn);
    cudaGetSymbolAddress((void**)&xp,  g_xp);
    cudaGetSymbolAddress((void**)&wkp, g_wkp);
    cudaGetSymbolAddress((void**)&wop, g_wop);
    cudaGetSymbolAddress((void**)&ap,  g_ap);
    cudaGetSymbolAddress((void**)&inv, g_inv);
    cudaGetSymbolAddress((void**)&ct,  g_cos);
    cudaGetSymbolAddress((void**)&st,  g_sin);

    cudaFuncSetAttribute(gemm_packed_kernel, cudaFuncAttributeMaxDynamicSharedMemorySize, GEMM_SMEM);
    cudaFuncSetAttribute(attn_mma_kernel,    cudaFuncAttributeMaxDynamicSharedMemorySize, ATT_SMEM);

    // 0) rope tables + pack operands (tf32 rna rounding folded in)
    freq_kernel<<<1, 64>>>(inv);
    trig_kernel<<<(TT * 64) / 256, 256>>>(inv, ct, st);
    packA_kernel<<<dim3(DD / 64, MROWS / 32), 256>>>(x, (float4*)xp, MROWS, DD);
    packB_kernel<<<(DD / 4 * N3 + 255) / 256, 256>>>(Wkqv, (float4*)wkp, DD, N3);
    packB_kernel<<<(DD / 4 * DD + 255) / 256, 256>>>(Wo, (float4*)wop, DD, DD);

    // 1) kqv = x @ Wkqv + bkqv, fused rope + tf32 rounding
    gemm_packed_kernel<<<dim3(N3 / 128, MROWS / 128), 256, GEMM_SMEM>>>(
        (const float4*)xp, (const float4*)wkp, bkqv, kqv, MROWS, N3, DD, 1, ct, st);

    // 2) causal flash attention -> g_attn
    attn_mma_kernel<<<dim3(TT / 128, BB * HH), 256, ATT_SMEM>>>();

    // 3) pack attention output, then out = attn @ Wo + bo
    packA_kernel<<<dim3(DD / 64, MROWS / 32), 256>>>(attn, (float4*)ap, MROWS, DD);
    gemm_packed_kernel<<<dim3(DD / 128, MROWS / 128), 256, GEMM_SMEM>>>(
        (const float4*)ap, (const float4*)wop, bo, out, MROWS, DD, DD, 0, ct, st);
}

// round 8
// speedup vs baseline: 1.1416x; 1.0304x over previous
#include <cuda_runtime.h>
#include <math.h>
#include <stdint.h>

#define BB    2
#define TT    2048
#define DD    2048
#define HH    16
#define DK    128
#define N3    (3*DD)
#define MROWS (BB*TT)   // 4096

// ---------------- scratch (device globals; no allocation allowed) ----------------
__device__ float g_kqv[(size_t)MROWS * N3];    // fp32 k|q|v (tf32-rounded, rope applied)
__device__ float g_attn[(size_t)MROWS * DD];   // attention output fp32
__device__ float g_xp[(size_t)MROWS * DD];     // x packed (tf32)   [ck][M] float4 cells
__device__ float g_wkp[(size_t)DD * N3];       // Wkqv packed       [ck][N] float4 cells
__device__ float g_wop[(size_t)DD * DD];       // Wo packed
__device__ float g_ap[(size_t)MROWS * DD];     // attn packed
__device__ float g_inv[64];
__device__ float g_cos[TT * 64];
__device__ float g_sin[TT * 64];

// ---------------- PTX helpers ----------------
__device__ __forceinline__ uint32_t smem_u32(const void* p) {
    return (uint32_t)__cvta_generic_to_shared(p);
}
__device__ __forceinline__ void cp16s(uint32_t dst, const void* src) {
    asm volatile("cp.async.cg.shared.global [%0], [%1], 16;\n" :: "r"(dst), "l"(src));
}
__device__ __forceinline__ void cp16(void* dst, const void* src) {
    asm volatile("cp.async.cg.shared.global [%0], [%1], 16;\n"
                 :: "r"(smem_u32(dst)), "l"(src));
}
__device__ __forceinline__ void cp_commit() {
    asm volatile("cp.async.commit_group;\n");
}
template<int N>
__device__ __forceinline__ void cp_wait() {
    asm volatile("cp.async.wait_group %0;\n" :: "n"(N));
}
__device__ __forceinline__ uint32_t f2tf(float f) {
    uint32_t r;
    asm("cvt.rna.tf32.f32 %0, %1;" : "=r"(r) : "f"(f));
    return r;
}
__device__ __forceinline__ float tfr(float f) {
    return __uint_as_float(f2tf(f));
}
__device__ __forceinline__ void mma_tf32(float c[4],
                                         uint32_t a0, uint32_t a1, uint32_t a2, uint32_t a3,
                                         uint32_t b0, uint32_t b1) {
    asm volatile(
        "mma.sync.aligned.m16n8k8.row.col.f32.tf32.tf32.f32 "
        "{%0,%1,%2,%3}, {%4,%5,%6,%7}, {%8,%9}, {%0,%1,%2,%3};\n"
        : "+f"(c[0]), "+f"(c[1]), "+f"(c[2]), "+f"(c[3])
        : "r"(a0), "r"(a1), "r"(a2), "r"(a3), "r"(b0), "r"(b1));
}
#define FU(x) __float_as_uint(x)

// ---------------- pack kernels: fragment-order gmem layout ----------------
// Cell (ck, i), ck = kg*4+tg, holds (X[i][kb], X[i][kb+4], X[i][kb+8], X[i][kb+12]),
// kb = kg*16+tg, as float4 at out[ck*Len + i]. Values tf32(rna)-rounded.

__global__ void packA_kernel(const float* __restrict__ in, float4* __restrict__ out,
                             int Mt, int K)
{
    __shared__ float tile[32][65];
    const int k0 = blockIdx.x * 64;
    const int m0 = blockIdx.y * 32;
    const int t  = threadIdx.x;
    #pragma unroll
    for (int i = 0; i < 2; i++) {
        int u = t + (i << 8);
        int m = u >> 4;
        int kc = u & 15;
        float4 v = *(const float4*)&in[(size_t)(m0 + m) * K + k0 + kc * 4];
        tile[m][kc * 4 + 0] = v.x;
        tile[m][kc * 4 + 1] = v.y;
        tile[m][kc * 4 + 2] = v.z;
        tile[m][kc * 4 + 3] = v.w;
    }
    __syncthreads();
    #pragma unroll
    for (int i = 0; i < 2; i++) {
        int u  = t + (i << 8);
        int ck = u >> 5;
        int m  = u & 31;
        int kg = ck >> 2, tg = ck & 3;
        int kb = kg * 16 + tg;
        float4 v;
        v.x = tfr(tile[m][kb]);
        v.y = tfr(tile[m][kb + 4]);
        v.z = tfr(tile[m][kb + 8]);
        v.w = tfr(tile[m][kb + 12]);
        out[(size_t)((k0 / 16 + kg) * 4 + tg) * Mt + m0 + m] = v;
    }
}

__global__ void packB_kernel(const float* __restrict__ W, float4* __restrict__ out,
                             int K, int N)
{
    int idx = blockIdx.x * 256 + threadIdx.x;
    int total = (K / 4) * N;
    if (idx >= total) return;
    int ck = idx / N;
    int n  = idx - ck * N;
    int kg = ck >> 2, tg = ck & 3;
    int kb = kg * 16 + tg;
    float4 v;
    v.x = tfr(W[(size_t)kb * N + n]);
    v.y = tfr(W[(size_t)(kb + 4) * N + n]);
    v.z = tfr(W[(size_t)(kb + 8) * N + n]);
    v.w = tfr(W[(size_t)(kb + 12) * N + n]);
    out[(size_t)ck * N + n] = v;
}

// ---------------- packed TF32 GEMM: CTA 128x128, warp 64x32, BK=32/stage, 3 stages ----------------
// Stage cells (16B): A 8*130 + B 8*130, stride 130 => conflict-free LDS.128.
#define HALF_CELLS  1040                     // 8*130
#define STAGE_BYTES (2 * HALF_CELLS * 16)    // 33280
#define GEMM_SMEM   (3 * STAGE_BYTES)        // 99840

__global__ __launch_bounds__(256, 2)
void gemm_packed_kernel(const float4* __restrict__ Ap, const float4* __restrict__ Bp,
                        const float* __restrict__ bias, float* __restrict__ C,
                        int Mt, int Nt, int K, int mode,
                        const float* __restrict__ ct, const float* __restrict__ st)
{
    extern __shared__ char smx[];
    const uint32_t sb = smem_u32(smx);
    const int t    = threadIdx.x;
    const int wid  = t >> 5;
    const int lane = t & 31;
    const int g    = lane >> 2;
    const int tg   = lane & 3;
    const int wm   = wid & 1;
    const int wn   = wid >> 1;
    const int rowBase = blockIdx.y * 128;
    const int colBase = blockIdx.x * 128;

    float acc[4][4][4];
    #pragma unroll
    for (int mi = 0; mi < 4; mi++)
        #pragma unroll
        for (int ni = 0; ni < 4; ni++)
            #pragma unroll
            for (int r = 0; r < 4; r++) acc[mi][ni][r] = 0.0f;

    const int NK = K / 32;                  // 32-k tiles

    auto issue = [&](int kt) {
        const uint32_t base = sb + (kt % 3) * STAGE_BYTES;
        #pragma unroll
        for (int i = 0; i < 8; i++) {
            const int u = t + (i << 8);     // 0..2047
            if (u < 1024) {
                const int tg8 = u >> 7, mm = u & 127;
                cp16s(base + (tg8 * 130 + mm) * 16,
                      Ap + ((size_t)(kt * 8 + tg8) * Mt + rowBase + mm));
            } else {
                const int v = u - 1024;
                const int tg8 = v >> 7, mm = v & 127;
                cp16s(base + (HALF_CELLS + tg8 * 130 + mm) * 16,
                      Bp + ((size_t)(kt * 8 + tg8) * Nt + colBase + mm));
            }
        }
        cp_commit();
    };

    issue(0);
    issue(1);

    for (int kt = 0; kt < NK; kt++) {
        cp_wait<1>();
        __syncthreads();
        if (kt + 2 < NK) issue(kt + 2);

        const float* Stg = (const float*)(smx + (kt % 3) * STAGE_BYTES);

        #pragma unroll
        for (int sub = 0; sub < 2; sub++) {
            const float* Asl = Stg + (sub * 4 + tg) * 130 * 4;
            const float* Bsl = Stg + (HALF_CELLS + (sub * 4 + tg) * 130) * 4;

            float4 A0[4], A1[4], Bv[4];
            #pragma unroll
            for (int mi = 0; mi < 4; mi++) {
                const int mr = wm * 64 + mi * 16 + g;
                A0[mi] = *(const float4*)&Asl[mr * 4];
                A1[mi] = *(const float4*)&Asl[(mr + 8) * 4];
            }
            #pragma unroll
            for (int ni = 0; ni < 4; ni++)
                Bv[ni] = *(const float4*)&Bsl[(wn * 32 + ni * 8 + g) * 4];

            #pragma unroll
            for (int mi = 0; mi < 4; mi++)
                #pragma unroll
                for (int ni = 0; ni < 4; ni++) {
                    mma_tf32(acc[mi][ni], FU(A0[mi].x), FU(A1[mi].x), FU(A0[mi].y), FU(A1[mi].y),
                             FU(Bv[ni].x), FU(Bv[ni].y));
                    mma_tf32(acc[mi][ni], FU(A0[mi].z), FU(A1[mi].z), FU(A0[mi].w), FU(A1[mi].w),
                             FU(Bv[ni].z), FU(Bv[ni].w));
                }
        }
        // no bottom barrier: with 3 stages, issue(kt+2) targets stage (kt-1)%3,
        // whose readers all passed this iteration's top barrier.
    }
    cp_wait<0>();

    // ---- epilogue: bias (+fused rope + tf32 rounding when mode==1) ----
    #pragma unroll
    for (int mi = 0; mi < 4; mi++) {
        const int r0 = rowBase + wm * 64 + mi * 16 + g;
        const int r1 = r0 + 8;
        #pragma unroll
        for (int ni = 0; ni < 4; ni++) {
            const int c = colBase + wn * 32 + ni * 8 + tg * 2;
            const float2 b2 = *(const float2*)&bias[c];
            float v0 = acc[mi][ni][0] + b2.x;
            float v1 = acc[mi][ni][1] + b2.y;
            float v2 = acc[mi][ni][2] + b2.x;
            float v3 = acc[mi][ni][3] + b2.y;
            if (mode == 1) {
                const int sect = c >> 11;
                if (sect < 2) {
                    const int pj = (c & 127) >> 1;
                    const float c0 = ct[(r0 & (TT - 1)) * 64 + pj];
                    const float s0 = st[(r0 & (TT - 1)) * 64 + pj];
                    const float c1 = ct[(r1 & (TT - 1)) * 64 + pj];
                    const float s1 = st[(r1 & (TT - 1)) * 64 + pj];
                    float e0 = v0 * c0 - v1 * s0, o0 = v0 * s0 + v1 * c0;
                    float e1 = v2 * c1 - v3 * s1, o1 = v2 * s1 + v3 * c1;
                    v0 = e0; v1 = o0; v2 = e1; v3 = o1;
                }
                v0 = tfr(v0); v1 = tfr(v1); v2 = tfr(v2); v3 = tfr(v3);
            }
            *(float2*)&C[(size_t)r0 * Nt + c] = make_float2(v0, v1);
            *(float2*)&C[(size_t)r1 * Nt + c] = make_float2(v2, v3);
        }
    }
}

// ---------------- RoPE tables ----------------
__global__ void freq_kernel(float* __restrict__ inv)
{
    int p = threadIdx.x;
    if (p < 64) inv[p] = (float)pow(10000.0, -(double)p / 64.0);
}

__global__ void trig_kernel(const float* __restrict__ inv,
                            float* __restrict__ ct, float* __restrict__ st)
{
    int idx = blockIdx.x * blockDim.x + threadIdx.x;
    if (idx >= TT * 64) return;
    int tpos = idx >> 6;
    int p    = idx & 63;
    float ang = (float)tpos * inv[p];
    float s, c;
    sincosf(ang, &s, &c);
    ct[idx] = c;
    st[idx] = s;
}

// ---------------- Flash attention (tf32 tensor cores, causal) ----------------
#define LDKK 132
#define LDVV 136
#define LDPK 132
#define ATT_SMEM ((2*64*LDKK + 2*64*LDVV + 128*LDPK) * 4)   // 200 KB

__global__ __launch_bounds__(256, 1)
void attn_mma_kernel()
{
    extern __shared__ float sm[];
    float* Ks = sm;                                  // [2][64][LDKK]
    float* Vs = Ks + 2 * 64 * LDKK;                  // [2][64][LDVV]
    float* Ps = Vs + 2 * 64 * LDVV;                  // [128][LDPK] (also Q staging)

    const int t    = threadIdx.x;
    const int lane = t & 31;
    const int w    = t >> 5;
    const int g    = lane >> 2;
    const int tg   = lane & 3;
    const int bh = blockIdx.y;
    const int b  = bh >> 4;
    const int h  = bh & 15;
    const int qt = (int)gridDim.x - 1 - (int)blockIdx.x;
    const int qbase = qt * 128;
    const size_t rowbase = (size_t)b * TT;
    const int hoff = h * DK;
    const float scale = 0.08838834764831845f;

    for (int u = t; u < 128 * 32; u += 256) {
        int qi = u >> 5;
        int c  = u & 31;
        float4 v = *(const float4*)&g_kqv[(rowbase + qbase + qi) * N3 + DD + hoff + c * 4];
        *(float4*)&Ps[qi * LDPK + c * 4] = v;
    }
    __syncthreads();
    const int qr = w * 16 + g;
    uint32_t qf[16][4];
    #pragma unroll
    for (int ks = 0; ks < 16; ks++) {
        qf[ks][0] = *(const uint32_t*)&Ps[qr * LDPK + ks * 8 + tg];
        qf[ks][1] = *(const uint32_t*)&Ps[(qr + 8) * LDPK + ks * 8 + tg];
        qf[ks][2] = *(const uint32_t*)&Ps[qr * LDPK + ks * 8 + tg + 4];
        qf[ks][3] = *(const uint32_t*)&Ps[(qr + 8) * LDPK + ks * 8 + tg + 4];
    }
    __syncthreads();

    float oacc[16][4];
    #pragma unroll
    for (int ni = 0; ni < 16; ni++)
        #pragma unroll
        for (int r = 0; r < 4; r++) oacc[ni][r] = 0.0f;
    float m0 = -1e30f, m1 = -1e30f, l0 = 0.0f, l1 = 0.0f;

    auto issue_tile = [&](int kt) {
        const int s = kt & 1;
        #pragma unroll
        for (int i = 0; i < 8; i++) {
            int u = t + i * 256;
            int r = u >> 5;
            int c = u & 31;
            const size_t grow = (rowbase + (size_t)kt * 64 + r) * N3;
            cp16(&Ks[s * 64 * LDKK + r * LDKK + c * 4], &g_kqv[grow + hoff + c * 4]);
            cp16(&Vs[s * 64 * LDVV + r * LDVV + c * 4], &g_kqv[grow + 2 * DD + hoff + c * 4]);
        }
        cp_commit();
    };

    const int nkt = 2 * qt + 2;
    issue_tile(0);

    for (int kt = 0; kt < nkt; kt++) {
        const int s = kt & 1;
        __syncthreads();
        if (kt + 1 < nkt) issue_tile(kt + 1);
        cp_wait<1>();
        __syncthreads();

        float sacc[8][4];
        #pragma unroll
        for (int ni = 0; ni < 8; ni++)
            #pragma unroll
            for (int r = 0; r < 4; r++) sacc[ni][r] = 0.0f;

        const float* Kb = Ks + s * 64 * LDKK;
        #pragma unroll
        for (int ks = 0; ks < 16; ks++) {
            #pragma unroll
            for (int ni = 0; ni < 8; ni++) {
                uint32_t b0 = *(const uint32_t*)&Kb[(ni * 8 + g) * LDKK + ks * 8 + tg];
                uint32_t b1 = *(const uint32_t*)&Kb[(ni * 8 + g) * LDKK + ks * 8 + tg + 4];
                mma_tf32(sacc[ni], qf[ks][0], qf[ks][1], qf[ks][2], qf[ks][3], b0, b1);
            }
        }

        const int r0 = qbase + w * 16 + g;
        const int r1 = r0 + 8;
        const int kb = kt * 64;
        float rm0 = -1e30f, rm1 = -1e30f;
        #pragma unroll
        for (int ni = 0; ni < 8; ni++) {
            const int c0 = kb + ni * 8 + 2 * tg;
            float v0 = sacc[ni][0] * scale; if (c0     > r0) v0 = -1e30f;
            float v1 = sacc[ni][1] * scale; if (c0 + 1 > r0) v1 = -1e30f;
            float v2 = sacc[ni][2] * scale; if (c0     > r1) v2 = -1e30f;
            float v3 = sacc[ni][3] * scale; if (c0 + 1 > r1) v3 = -1e30f;
            sacc[ni][0] = v0; sacc[ni][1] = v1; sacc[ni][2] = v2; sacc[ni][3] = v3;
            rm0 = fmaxf(rm0, fmaxf(v0, v1));
            rm1 = fmaxf(rm1, fmaxf(v2, v3));
        }
        rm0 = fmaxf(rm0, __shfl_xor_sync(0xffffffffu, rm0, 1));
        rm0 = fmaxf(rm0, __shfl_xor_sync(0xffffffffu, rm0, 2));
        rm1 = fmaxf(rm1, __shfl_xor_sync(0xffffffffu, rm1, 1));
        rm1 = fmaxf(rm1, __shfl_xor_sync(0xffffffffu, rm1, 2));

        const float mn0 = fmaxf(m0, rm0);
        const float mn1 = fmaxf(m1, rm1);
        const float f0 = __expf(m0 - mn0);
        const float f1 = __expf(m1 - mn1);
        m0 = mn0; m1 = mn1;

        float ps0 = 0.0f, ps1 = 0.0f;
        #pragma unroll
        for (int ni = 0; ni < 8; ni++) {
            float p0 = __expf(sacc[ni][0] - mn0);
            float p1 = __expf(sacc[ni][1] - mn0);
            float p2 = __expf(sacc[ni][2] - mn1);
            float p3 = __expf(sacc[ni][3] - mn1);
            sacc[ni][0] = p0; sacc[ni][1] = p1; sacc[ni][2] = p2; sacc[ni][3] = p3;
            ps0 += p0 + p1;
            ps1 += p2 + p3;
        }
        ps0 += __shfl_xor_sync(0xffffffffu, ps0, 1);
        ps0 += __shfl_xor_sync(0xffffffffu, ps0, 2);
        ps1 += __shfl_xor_sync(0xffffffffu, ps1, 1);
        ps1 += __shfl_xor_sync(0xffffffffu, ps1, 2);
        l0 = l0 * f0 + ps0;
        l1 = l1 * f1 + ps1;

        #pragma unroll
        for (int ni = 0; ni < 16; ni++) {
            oacc[ni][0] *= f0; oacc[ni][1] *= f0;
            oacc[ni][2] *= f1; oacc[ni][3] *= f1;
        }

        const int pq = w * 16 + g;
        #pragma unroll
        for (int ni = 0; ni < 8; ni++) {
            *(float2*)&Ps[pq * LDPK + ni * 8 + 2 * tg]       = make_float2(sacc[ni][0], sacc[ni][1]);
            *(float2*)&Ps[(pq + 8) * LDPK + ni * 8 + 2 * tg] = make_float2(sacc[ni][2], sacc[ni][3]);
        }
        __syncthreads();

        // ---- O += P @ V  (single tf32 pass) ----
        const float* Vb = Vs + s * 64 * LDVV;
        #pragma unroll
        for (int ks2 = 0; ks2 < 8; ks2++) {
            uint32_t h0 = f2tf(Ps[pq * LDPK + ks2 * 8 + tg]);
            uint32_t h1 = f2tf(Ps[(pq + 8) * LDPK + ks2 * 8 + tg]);
            uint32_t h2 = f2tf(Ps[pq * LDPK + ks2 * 8 + tg + 4]);
            uint32_t h3 = f2tf(Ps[(pq + 8) * LDPK + ks2 * 8 + tg + 4]);
            #pragma unroll
            for (int ni = 0; ni < 16; ni++) {
                uint32_t b0 = *(const uint32_t*)&Vb[(ks2 * 8 + tg) * LDVV + ni * 8 + g];
                uint32_t b1 = *(const uint32_t*)&Vb[(ks2 * 8 + tg + 4) * LDVV + ni * 8 + g];
                mma_tf32(oacc[ni], h0, h1, h2, h3, b0, b1);
            }
        }
    }

    // ---- epilogue: O / l -> g_attn fp32 ----
    const float il0 = 1.0f / l0;
    const float il1 = 1.0f / l1;
    const size_t row0 = rowbase + qbase + w * 16 + g;
    #pragma unroll
    for (int ni = 0; ni < 16; ni++) {
        const int col = hoff + ni * 8 + 2 * tg;
        *(float2*)&g_attn[row0 * DD + col] =
            make_float2(oacc[ni][0] * il0, oacc[ni][1] * il0);
        *(float2*)&g_attn[(row0 + 8) * DD + col] =
            make_float2(oacc[ni][2] * il1, oacc[ni][3] * il1);
    }
}

// ---------------- launch ----------------
extern "C" void kernel_launch(void* const* d_in, const int* in_sizes, int n_in,
                              void* d_out, int out_size)
{
    const float* x    = (const float*)d_in[0];
    const float* Wkqv = (const float*)d_in[1];
    const float* bkqv = (const float*)d_in[2];
    const float* Wo   = (const float*)d_in[3];
    const float* bo   = (const float*)d_in[4];
    float* out = (float*)d_out;

    float *kqv, *attn, *xp, *wkp, *wop, *ap, *inv, *ct, *st;
    cudaGetSymbolAddress((void**)&kqv, g_kqv);
    cudaGetSymbolAddress((void**)&attn, g_attn);
    cudaGetSymbolAddress((void**)&xp,  g_xp);
    cudaGetSymbolAddress((void**)&wkp, g_wkp);
    cudaGetSymbolAddress((void**)&wop, g_wop);
    cudaGetSymbolAddress((void**)&ap,  g_ap);
    cudaGetSymbolAddress((void**)&inv, g_inv);
    cudaGetSymbolAddress((void**)&ct,  g_cos);
    cudaGetSymbolAddress((void**)&st,  g_sin);

    cudaFuncSetAttribute(gemm_packed_kernel, cudaFuncAttributeMaxDynamicSharedMemorySize, GEMM_SMEM);
    cudaFuncSetAttribute(attn_mma_kernel,    cudaFuncAttributeMaxDynamicSharedMemorySize, ATT_SMEM);

    // 0) rope tables + pack operands (tf32 rna rounding folded in)
    freq_kernel<<<1, 64>>>(inv);
    trig_kernel<<<(TT * 64) / 256, 256>>>(inv, ct, st);
    packA_kernel<<<dim3(DD / 64, MROWS / 32), 256>>>(x, (float4*)xp, MROWS, DD);
    packB_kernel<<<(DD / 4 * N3 + 255) / 256, 256>>>(Wkqv, (float4*)wkp, DD, N3);
    packB_kernel<<<(DD / 4 * DD + 255) / 256, 256>>>(Wo, (float4*)wop, DD, DD);

    // 1) kqv = x @ Wkqv + bkqv, fused rope + tf32 rounding
    gemm_packed_kernel<<<dim3(N3 / 128, MROWS / 128), 256, GEMM_SMEM>>>(
        (const float4*)xp, (const float4*)wkp, bkqv, kqv, MROWS, N3, DD, 1, ct, st);

    // 2) causal flash attention -> g_attn
    attn_mma_kernel<<<dim3(TT / 128, BB * HH), 256, ATT_SMEM>>>();

    // 3) pack attention output, then out = attn @ Wo + bo
    packA_kernel<<<dim3(DD / 64, MROWS / 32), 256>>>(attn, (float4*)ap, MROWS, DD);
    gemm_packed_kernel<<<dim3(DD / 128, MROWS / 128), 256, GEMM_SMEM>>>(
        (const float4*)ap, (const float4*)wop, bo, out, MROWS, DD, DD, 0, ct, st);
}

// round 9
// speedup vs baseline: 1.1449x; 1.0029x over previous
#include <cuda_runtime.h>
#include <math.h>
#include <stdint.h>

#define BB    2
#define TT    2048
#define DD    2048
#define HH    16
#define DK    128
#define N3    (3*DD)
#define MROWS (BB*TT)   // 4096

// ---------------- scratch (device globals; no allocation allowed) ----------------
__device__ float g_kqv[(size_t)MROWS * N3];    // fp32 k|q|v (tf32-rounded, rope applied)
__device__ float g_attn[(size_t)MROWS * DD];   // attention output fp32
__device__ float g_xp[(size_t)MROWS * DD];     // x packed (tf32)   [ck][M] float4 cells
__device__ float g_wkp[(size_t)DD * N3];       // Wkqv packed       [ck][N] float4 cells
__device__ float g_wop[(size_t)DD * DD];       // Wo packed
__device__ float g_ap[(size_t)MROWS * DD];     // attn packed
__device__ float g_inv[64];
__device__ float g_cos[TT * 64];
__device__ float g_sin[TT * 64];

// ---------------- PTX helpers ----------------
__device__ __forceinline__ uint32_t smem_u32(const void* p) {
    return (uint32_t)__cvta_generic_to_shared(p);
}
__device__ __forceinline__ void cp16s(uint32_t dst, const void* src) {
    asm volatile("cp.async.cg.shared.global [%0], [%1], 16;\n" :: "r"(dst), "l"(src));
}
__device__ __forceinline__ void cp16(void* dst, const void* src) {
    asm volatile("cp.async.cg.shared.global [%0], [%1], 16;\n"
                 :: "r"(smem_u32(dst)), "l"(src));
}
__device__ __forceinline__ void cp_commit() {
    asm volatile("cp.async.commit_group;\n");
}
template<int N>
__device__ __forceinline__ void cp_wait() {
    asm volatile("cp.async.wait_group %0;\n" :: "n"(N));
}
__device__ __forceinline__ uint32_t f2tf(float f) {
    uint32_t r;
    asm("cvt.rna.tf32.f32 %0, %1;" : "=r"(r) : "f"(f));
    return r;
}
__device__ __forceinline__ float tfr(float f) {
    return __uint_as_float(f2tf(f));
}
__device__ __forceinline__ void mma_tf32(float c[4],
                                         uint32_t a0, uint32_t a1, uint32_t a2, uint32_t a3,
                                         uint32_t b0, uint32_t b1) {
    asm volatile(
        "mma.sync.aligned.m16n8k8.row.col.f32.tf32.tf32.f32 "
        "{%0,%1,%2,%3}, {%4,%5,%6,%7}, {%8,%9}, {%0,%1,%2,%3};\n"
        : "+f"(c[0]), "+f"(c[1]), "+f"(c[2]), "+f"(c[3])
        : "r"(a0), "r"(a1), "r"(a2), "r"(a3), "r"(b0), "r"(b1));
}
#define FU(x) __float_as_uint(x)

// ---------------- pack kernels: fragment-order gmem layout ----------------
__global__ void packA_kernel(const float* __restrict__ in, float4* __restrict__ out,
                             int Mt, int K)
{
    __shared__ float tile[32][65];
    const int k0 = blockIdx.x * 64;
    const int m0 = blockIdx.y * 32;
    const int t  = threadIdx.x;
    #pragma unroll
    for (int i = 0; i < 2; i++) {
        int u = t + (i << 8);
        int m = u >> 4;
        int kc = u & 15;
        float4 v = *(const float4*)&in[(size_t)(m0 + m) * K + k0 + kc * 4];
        tile[m][kc * 4 + 0] = v.x;
        tile[m][kc * 4 + 1] = v.y;
        tile[m][kc * 4 + 2] = v.z;
        tile[m][kc * 4 + 3] = v.w;
    }
    __syncthreads();
    #pragma unroll
    for (int i = 0; i < 2; i++) {
        int u  = t + (i << 8);
        int ck = u >> 5;
        int m  = u & 31;
        int kg = ck >> 2, tg = ck & 3;
        int kb = kg * 16 + tg;
        float4 v;
        v.x = tfr(tile[m][kb]);
        v.y = tfr(tile[m][kb + 4]);
        v.z = tfr(tile[m][kb + 8]);
        v.w = tfr(tile[m][kb + 12]);
        out[(size_t)((k0 / 16 + kg) * 4 + tg) * Mt + m0 + m] = v;
    }
}

__global__ void packB_kernel(const float* __restrict__ W, float4* __restrict__ out,
                             int K, int N)
{
    int idx = blockIdx.x * 256 + threadIdx.x;
    int total = (K / 4) * N;
    if (idx >= total) return;
    int ck = idx / N;
    int n  = idx - ck * N;
    int kg = ck >> 2, tg = ck & 3;
    int kb = kg * 16 + tg;
    float4 v;
    v.x = tfr(W[(size_t)kb * N + n]);
    v.y = tfr(W[(size_t)(kb + 4) * N + n]);
    v.z = tfr(W[(size_t)(kb + 8) * N + n]);
    v.w = tfr(W[(size_t)(kb + 12) * N + n]);
    out[(size_t)ck * N + n] = v;
}

// ---------------- packed TF32 GEMM: CTA 128x128, warp 64x32, BK=32/stage, 3 stages ----------------
#define HALF_CELLS  1040                     // 8*130
#define STAGE_BYTES (2 * HALF_CELLS * 16)    // 33280
#define GEMM_SMEM   (3 * STAGE_BYTES)        // 99840

__global__ __launch_bounds__(256, 2)
void gemm_packed_kernel(const float4* __restrict__ Ap, const float4* __restrict__ Bp,
                        const float* __restrict__ bias, float* __restrict__ C,
                        int Mt, int Nt, int K, int mode,
                        const float* __restrict__ ct, const float* __restrict__ st)
{
    extern __shared__ char smx[];
    const uint32_t sb = smem_u32(smx);
    const int t    = threadIdx.x;
    const int wid  = t >> 5;
    const int lane = t & 31;
    const int g    = lane >> 2;
    const int tg   = lane & 3;
    const int wm   = wid & 1;
    const int wn   = wid >> 1;
    const int rowBase = blockIdx.y * 128;
    const int colBase = blockIdx.x * 128;

    float acc[4][4][4];
    #pragma unroll
    for (int mi = 0; mi < 4; mi++)
        #pragma unroll
        for (int ni = 0; ni < 4; ni++)
            #pragma unroll
            for (int r = 0; r < 4; r++) acc[mi][ni][r] = 0.0f;

    const int NK = K / 32;

    auto issue = [&](int kt) {
        const uint32_t base = sb + (kt % 3) * STAGE_BYTES;
        #pragma unroll
        for (int i = 0; i < 8; i++) {
            const int u = t + (i << 8);
            if (u < 1024) {
                const int tg8 = u >> 7, mm = u & 127;
                cp16s(base + (tg8 * 130 + mm) * 16,
                      Ap + ((size_t)(kt * 8 + tg8) * Mt + rowBase + mm));
            } else {
                const int v = u - 1024;
                const int tg8 = v >> 7, mm = v & 127;
                cp16s(base + (HALF_CELLS + tg8 * 130 + mm) * 16,
                      Bp + ((size_t)(kt * 8 + tg8) * Nt + colBase + mm));
            }
        }
        cp_commit();
    };

    issue(0);
    issue(1);

    for (int kt = 0; kt < NK; kt++) {
        cp_wait<1>();
        __syncthreads();
        if (kt + 2 < NK) issue(kt + 2);

        const float* Stg = (const float*)(smx + (kt % 3) * STAGE_BYTES);

        #pragma unroll
        for (int sub = 0; sub < 2; sub++) {
            const float* Asl = Stg + (sub * 4 + tg) * 130 * 4;
            const float* Bsl = Stg + (HALF_CELLS + (sub * 4 + tg) * 130) * 4;

            float4 A0[4], A1[4], Bv[4];
            #pragma unroll
            for (int mi = 0; mi < 4; mi++) {
                const int mr = wm * 64 + mi * 16 + g;
                A0[mi] = *(const float4*)&Asl[mr * 4];
                A1[mi] = *(const float4*)&Asl[(mr + 8) * 4];
            }
            #pragma unroll
            for (int ni = 0; ni < 4; ni++)
                Bv[ni] = *(const float4*)&Bsl[(wn * 32 + ni * 8 + g) * 4];

            #pragma unroll
            for (int mi = 0; mi < 4; mi++)
                #pragma unroll
                for (int ni = 0; ni < 4; ni++) {
                    mma_tf32(acc[mi][ni], FU(A0[mi].x), FU(A1[mi].x), FU(A0[mi].y), FU(A1[mi].y),
                             FU(Bv[ni].x), FU(Bv[ni].y));
                    mma_tf32(acc[mi][ni], FU(A0[mi].z), FU(A1[mi].z), FU(A0[mi].w), FU(A1[mi].w),
                             FU(Bv[ni].z), FU(Bv[ni].w));
                }
        }
    }
    cp_wait<0>();

    // ---- epilogue: bias (+fused rope + tf32 rounding when mode==1) ----
    #pragma unroll
    for (int mi = 0; mi < 4; mi++) {
        const int r0 = rowBase + wm * 64 + mi * 16 + g;
        const int r1 = r0 + 8;
        #pragma unroll
        for (int ni = 0; ni < 4; ni++) {
            const int c = colBase + wn * 32 + ni * 8 + tg * 2;
            const float2 b2 = *(const float2*)&bias[c];
            float v0 = acc[mi][ni][0] + b2.x;
            float v1 = acc[mi][ni][1] + b2.y;
            float v2 = acc[mi][ni][2] + b2.x;
            float v3 = acc[mi][ni][3] + b2.y;
            if (mode == 1) {
                const int sect = c >> 11;
                if (sect < 2) {
                    const int pj = (c & 127) >> 1;
                    const float c0 = ct[(r0 & (TT - 1)) * 64 + pj];
                    const float s0 = st[(r0 & (TT - 1)) * 64 + pj];
                    const float c1 = ct[(r1 & (TT - 1)) * 64 + pj];
                    const float s1 = st[(r1 & (TT - 1)) * 64 + pj];
                    float e0 = v0 * c0 - v1 * s0, o0 = v0 * s0 + v1 * c0;
                    float e1 = v2 * c1 - v3 * s1, o1 = v2 * s1 + v3 * c1;
                    v0 = e0; v1 = o0; v2 = e1; v3 = o1;
                }
                v0 = tfr(v0); v1 = tfr(v1); v2 = tfr(v2); v3 = tfr(v3);
            }
            *(float2*)&C[(size_t)r0 * Nt + c] = make_float2(v0, v1);
            *(float2*)&C[(size_t)r1 * Nt + c] = make_float2(v2, v3);
        }
    }
}

// ---------------- RoPE tables ----------------
__global__ void freq_kernel(float* __restrict__ inv)
{
    int p = threadIdx.x;
    if (p < 64) inv[p] = (float)pow(10000.0, -(double)p / 64.0);
}

__global__ void trig_kernel(const float* __restrict__ inv,
                            float* __restrict__ ct, float* __restrict__ st)
{
    int idx = blockIdx.x * blockDim.x + threadIdx.x;
    if (idx >= TT * 64) return;
    int tpos = idx >> 6;
    int p    = idx & 63;
    float ang = (float)tpos * inv[p];
    float s, c;
    sincosf(ang, &s, &c);
    ct[idx] = c;
    st[idx] = s;
}

// ---------------- Flash attention (tf32 tensor cores, causal) ----------------
#define LDKK 132
#define LDVV 136
#define LDPK 132
#define ATT_SMEM ((2*64*LDKK + 2*64*LDVV + 128*LDPK) * 4)   // 200 KB

__global__ __launch_bounds__(256, 1)
void attn_mma_kernel()
{
    extern __shared__ float sm[];
    float* Ks = sm;                                  // [2][64][LDKK]
    float* Vs = Ks + 2 * 64 * LDKK;                  // [2][64][LDVV]
    float* Ps = Vs + 2 * 64 * LDVV;                  // [128][LDPK] (also Q staging)

    const int t    = threadIdx.x;
    const int lane = t & 31;
    const int w    = t >> 5;
    const int g    = lane >> 2;
    const int tg   = lane & 3;
    const int bh = blockIdx.y;
    const int b  = bh >> 4;
    const int h  = bh & 15;
    const int qt = (int)gridDim.x - 1 - (int)blockIdx.x;
    const int qbase = qt * 128;
    const size_t rowbase = (size_t)b * TT;
    const int hoff = h * DK;
    const float scale = 0.08838834764831845f;

    for (int u = t; u < 128 * 32; u += 256) {
        int qi = u >> 5;
        int c  = u & 31;
        float4 v = *(const float4*)&g_kqv[(rowbase + qbase + qi) * N3 + DD + hoff + c * 4];
        *(float4*)&Ps[qi * LDPK + c * 4] = v;
    }
    __syncthreads();
    const int qr = w * 16 + g;
    uint32_t qf[16][4];
    #pragma unroll
    for (int ks = 0; ks < 16; ks++) {
        qf[ks][0] = *(const uint32_t*)&Ps[qr * LDPK + ks * 8 + tg];
        qf[ks][1] = *(const uint32_t*)&Ps[(qr + 8) * LDPK + ks * 8 + tg];
        qf[ks][2] = *(const uint32_t*)&Ps[qr * LDPK + ks * 8 + tg + 4];
        qf[ks][3] = *(const uint32_t*)&Ps[(qr + 8) * LDPK + ks * 8 + tg + 4];
    }
    __syncthreads();

    float oacc[16][4];
    #pragma unroll
    for (int ni = 0; ni < 16; ni++)
        #pragma unroll
        for (int r = 0; r < 4; r++) oacc[ni][r] = 0.0f;
    float m0 = -1e30f, m1 = -1e30f, l0 = 0.0f, l1 = 0.0f;

    auto issue_tile = [&](int kt) {
        const int s = kt & 1;
        #pragma unroll
        for (int i = 0; i < 8; i++) {
            int u = t + i * 256;
            int r = u >> 5;
            int c = u & 31;
            const size_t grow = (rowbase + (size_t)kt * 64 + r) * N3;
            cp16(&Ks[s * 64 * LDKK + r * LDKK + c * 4], &g_kqv[grow + hoff + c * 4]);
            cp16(&Vs[s * 64 * LDVV + r * LDVV + c * 4], &g_kqv[grow + 2 * DD + hoff + c * 4]);
        }
        cp_commit();
    };

    const int nkt = 2 * qt + 2;
    issue_tile(0);

    for (int kt = 0; kt < nkt; kt++) {
        const int s = kt & 1;
        __syncthreads();
        if (kt + 1 < nkt) issue_tile(kt + 1);
        cp_wait<1>();
        __syncthreads();

        float sacc[8][4];
        #pragma unroll
        for (int ni = 0; ni < 8; ni++)
            #pragma unroll
            for (int r = 0; r < 4; r++) sacc[ni][r] = 0.0f;

        const float* Kb = Ks + s * 64 * LDKK;
        #pragma unroll
        for (int ks = 0; ks < 16; ks++) {
            #pragma unroll
            for (int ni = 0; ni < 8; ni++) {
                uint32_t b0 = *(const uint32_t*)&Kb[(ni * 8 + g) * LDKK + ks * 8 + tg];
                uint32_t b1 = *(const uint32_t*)&Kb[(ni * 8 + g) * LDKK + ks * 8 + tg + 4];
                mma_tf32(sacc[ni], qf[ks][0], qf[ks][1], qf[ks][2], qf[ks][3], b0, b1);
            }
        }

        const int r0 = qbase + w * 16 + g;
        const int r1 = r0 + 8;
        float rm0 = -1e30f, rm1 = -1e30f;
        if (kt >= 2 * qt) {
            // diagonal tiles: scale + causal mask
            const int kb = kt * 64;
            #pragma unroll
            for (int ni = 0; ni < 8; ni++) {
                const int c0 = kb + ni * 8 + 2 * tg;
                float v0 = sacc[ni][0] * scale; if (c0     > r0) v0 = -1e30f;
                float v1 = sacc[ni][1] * scale; if (c0 + 1 > r0) v1 = -1e30f;
                float v2 = sacc[ni][2] * scale; if (c0     > r1) v2 = -1e30f;
                float v3 = sacc[ni][3] * scale; if (c0 + 1 > r1) v3 = -1e30f;
                sacc[ni][0] = v0; sacc[ni][1] = v1; sacc[ni][2] = v2; sacc[ni][3] = v3;
                rm0 = fmaxf(rm0, fmaxf(v0, v1));
                rm1 = fmaxf(rm1, fmaxf(v2, v3));
            }
        } else {
            // interior tiles: fully unmasked (64*kt+63 <= 128*qt <= r0)
            #pragma unroll
            for (int ni = 0; ni < 8; ni++) {
                float v0 = sacc[ni][0] * scale;
                float v1 = sacc[ni][1] * scale;
                float v2 = sacc[ni][2] * scale;
                float v3 = sacc[ni][3] * scale;
                sacc[ni][0] = v0; sacc[ni][1] = v1; sacc[ni][2] = v2; sacc[ni][3] = v3;
                rm0 = fmaxf(rm0, fmaxf(v0, v1));
                rm1 = fmaxf(rm1, fmaxf(v2, v3));
            }
        }
        rm0 = fmaxf(rm0, __shfl_xor_sync(0xffffffffu, rm0, 1));
        rm0 = fmaxf(rm0, __shfl_xor_sync(0xffffffffu, rm0, 2));
        rm1 = fmaxf(rm1, __shfl_xor_sync(0xffffffffu, rm1, 1));
        rm1 = fmaxf(rm1, __shfl_xor_sync(0xffffffffu, rm1, 2));

        const float mn0 = fmaxf(m0, rm0);
        const float mn1 = fmaxf(m1, rm1);
        const float f0 = __expf(m0 - mn0);
        const float f1 = __expf(m1 - mn1);
        m0 = mn0; m1 = mn1;

        float ps0 = 0.0f, ps1 = 0.0f;
        #pragma unroll
        for (int ni = 0; ni < 8; ni++) {
            float p0 = __expf(sacc[ni][0] - mn0);
            float p1 = __expf(sacc[ni][1] - mn0);
            float p2 = __expf(sacc[ni][2] - mn1);
            float p3 = __expf(sacc[ni][3] - mn1);
            sacc[ni][0] = p0; sacc[ni][1] = p1; sacc[ni][2] = p2; sacc[ni][3] = p3;
            ps0 += p0 + p1;
            ps1 += p2 + p3;
        }
        ps0 += __shfl_xor_sync(0xffffffffu, ps0, 1);
        ps0 += __shfl_xor_sync(0xffffffffu, ps0, 2);
        ps1 += __shfl_xor_sync(0xffffffffu, ps1, 1);
        ps1 += __shfl_xor_sync(0xffffffffu, ps1, 2);
        l0 = l0 * f0 + ps0;
        l1 = l1 * f1 + ps1;

        #pragma unroll
        for (int ni = 0; ni < 16; ni++) {
            oacc[ni][0] *= f0; oacc[ni][1] *= f0;
            oacc[ni][2] *= f1; oacc[ni][3] *= f1;
        }

        const int pq = w * 16 + g;
        #pragma unroll
        for (int ni = 0; ni < 8; ni++) {
            *(float2*)&Ps[pq * LDPK + ni * 8 + 2 * tg]       = make_float2(sacc[ni][0], sacc[ni][1]);
            *(float2*)&Ps[(pq + 8) * LDPK + ni * 8 + 2 * tg] = make_float2(sacc[ni][2], sacc[ni][3]);
        }
        // P rows are warp-private (each warp reads only its own 16 q-rows);
        // cross-lane visibility within the warp only -> warp sync suffices.
        __syncwarp();

        // ---- O += P @ V  (single tf32 pass) ----
        const float* Vb = Vs + s * 64 * LDVV;
        #pragma unroll
        for (int ks2 = 0; ks2 < 8; ks2++) {
            uint32_t h0 = f2tf(Ps[pq * LDPK + ks2 * 8 + tg]);
            uint32_t h1 = f2tf(Ps[(pq + 8) * LDPK + ks2 * 8 + tg]);
            uint32_t h2 = f2tf(Ps[pq * LDPK + ks2 * 8 + tg + 4]);
            uint32_t h3 = f2tf(Ps[(pq + 8) * LDPK + ks2 * 8 + tg + 4]);
            #pragma unroll
            for (int ni = 0; ni < 16; ni++) {
                uint32_t b0 = *(const uint32_t*)&Vb[(ks2 * 8 + tg) * LDVV + ni * 8 + g];
                uint32_t b1 = *(const uint32_t*)&Vb[(ks2 * 8 + tg + 4) * LDVV + ni * 8 + g];
                mma_tf32(oacc[ni], h0, h1, h2, h3, b0, b1);
            }
        }
    }

    // ---- epilogue: O / l -> g_attn fp32 ----
    const float il0 = 1.0f / l0;
    const float il1 = 1.0f / l1;
    const size_t row0 = rowbase + qbase + w * 16 + g;
    #pragma unroll
    for (int ni = 0; ni < 16; ni++) {
        const int col = hoff + ni * 8 + 2 * tg;
        *(float2*)&g_attn[row0 * DD + col] =
            make_float2(oacc[ni][0] * il0, oacc[ni][1] * il0);
        *(float2*)&g_attn[(row0 + 8) * DD + col] =
            make_float2(oacc[ni][2] * il1, oacc[ni][3] * il1);
    }
}

// ---------------- launch ----------------
extern "C" void kernel_launch(void* const* d_in, const int* in_sizes, int n_in,
                              void* d_out, int out_size)
{
    const float* x    = (const float*)d_in[0];
    const float* Wkqv = (const float*)d_in[1];
    const float* bkqv = (const float*)d_in[2];
    const float* Wo   = (const float*)d_in[3];
    const float* bo   = (const float*)d_in[4];
    float* out = (float*)d_out;

    float *kqv, *attn, *xp, *wkp, *wop, *ap, *inv, *ct, *st;
    cudaGetSymbolAddress((void**)&kqv, g_kqv);
    cudaGetSymbolAddress((void**)&attn, g_attn);
    cudaGetSymbolAddress((void**)&xp,  g_xp);
    cudaGetSymbolAddress((void**)&wkp, g_wkp);
    cudaGetSymbolAddress((void**)&wop, g_wop);
    cudaGetSymbolAddress((void**)&ap,  g_ap);
    cudaGetSymbolAddress((void**)&inv, g_inv);
    cudaGetSymbolAddress((void**)&ct,  g_cos);
    cudaGetSymbolAddress((void**)&st,  g_sin);

    cudaFuncSetAttribute(gemm_packed_kernel, cudaFuncAttributeMaxDynamicSharedMemorySize, GEMM_SMEM);
    cudaFuncSetAttribute(attn_mma_kernel,    cudaFuncAttributeMaxDynamicSharedMemorySize, ATT_SMEM);

    // 0) rope tables + pack operands (tf32 rna rounding folded in)
    freq_kernel<<<1, 64>>>(inv);
    trig_kernel<<<(TT * 64) / 256, 256>>>(inv, ct, st);
    packA_kernel<<<dim3(DD / 64, MROWS / 32), 256>>>(x, (float4*)xp, MROWS, DD);
    packB_kernel<<<(DD / 4 * N3 + 255) / 256, 256>>>(Wkqv, (float4*)wkp, DD, N3);
    packB_kernel<<<(DD / 4 * DD + 255) / 256, 256>>>(Wo, (float4*)wop, DD, DD);

    // 1) kqv = x @ Wkqv + bkqv, fused rope + tf32 rounding
    gemm_packed_kernel<<<dim3(N3 / 128, MROWS / 128), 256, GEMM_SMEM>>>(
        (const float4*)xp, (const float4*)wkp, bkqv, kqv, MROWS, N3, DD, 1, ct, st);

    // 2) causal flash attention -> g_attn
    attn_mma_kernel<<<dim3(TT / 128, BB * HH), 256, ATT_SMEM>>>();

    // 3) pack attention output, then out = attn @ Wo + bo
    packA_kernel<<<dim3(DD / 64, MROWS / 32), 256>>>(attn, (float4*)ap, MROWS, DD);
    gemm_packed_kernel<<<dim3(DD / 128, MROWS / 128), 256, GEMM_SMEM>>>(
        (const float4*)ap, (const float4*)wop, bo, out, MROWS, DD, DD, 0, ct, st);
}